// round 2
// baseline (speedup 1.0000x reference)
#include <cuda_runtime.h>
#include <math.h>

// Problem dims
#define C_   3
#define T_   100
#define B_   512
#define F_   128
#define HX_  128
#define HZ_  128
#define H_   256
#define EH_  128
#define L_   64

#define NB_   48   // CTAs per channel in sequential kernel
#define RMAX_ 11   // max batch rows per CTA (512/48 -> 10 or 11)

// Scratch (device globals: allocations are forbidden)
__device__ float g_PE[(size_t)C_ * T_ * B_ * EH_];  // x_phi@We_x + be
__device__ float g_PI[(size_t)C_ * T_ * B_ * H_];   // x_phi@Wih_x + bih + bhh
__device__ float g_Hs[(size_t)C_ * T_ * B_ * H_];   // h at step input
__device__ float g_Zs[(size_t)C_ * T_ * B_ * HZ_];  // z_phi per step

// ---------------------------------------------------------------------------
// 128x128x128 block GEMM: acc(8x8 per thread) += As(row-major) @ Ws(row-major)
// 256 threads: thread (tr,tc) = (tid>>4, tid&15) owns rows tr*8.., cols tc*8..
// ---------------------------------------------------------------------------
__device__ __forceinline__ void gemm128(const float* __restrict__ As,
                                        const float* __restrict__ Ws,
                                        float acc[8][8]) {
    const int tc = threadIdx.x & 15;
    const int tr = threadIdx.x >> 4;
    const float* ap = As + tr * 8 * 128;
    const float* bp = Ws + tc * 8;
#pragma unroll 4
    for (int k = 0; k < 128; ++k) {
        const float4 b0 = *reinterpret_cast<const float4*>(bp + k * 128);
        const float4 b1 = *reinterpret_cast<const float4*>(bp + k * 128 + 4);
        float a[8];
#pragma unroll
        for (int i = 0; i < 8; ++i) a[i] = ap[i * 128 + k];
        const float bv[8] = {b0.x, b0.y, b0.z, b0.w, b1.x, b1.y, b1.z, b1.w};
#pragma unroll
        for (int i = 0; i < 8; ++i)
#pragma unroll
            for (int j = 0; j < 8; ++j)
                acc[i][j] = fmaf(a[i], bv[j], acc[i][j]);
    }
}

// Load a 128x128 fp32 tile (row stride ld, 16B-aligned rows) into smem
__device__ __forceinline__ void load_tile(float* dst, const float* __restrict__ src,
                                          int ld) {
    for (int idx = threadIdx.x; idx < 128 * 32; idx += 256) {
        const int r = idx >> 5;
        const int c4 = idx & 31;
        reinterpret_cast<float4*>(dst)[(r << 5) + c4] =
            *reinterpret_cast<const float4*>(src + (size_t)r * ld + (c4 << 2));
    }
}

__device__ __forceinline__ void zero_acc(float acc[8][8]) {
#pragma unroll
    for (int i = 0; i < 8; ++i)
#pragma unroll
        for (int j = 0; j < 8; ++j) acc[i][j] = 0.f;
}

// ---------------------------------------------------------------------------
// Kernel A: PE = (x@Wx+bx)@We_x + be ;  PI = (x@Wx+bx)@Wih_x + bih + bhh
// grid (4 btiles, T, C), 256 threads, 128KB dynamic smem (As + Ws)
// ---------------------------------------------------------------------------
__global__ void __launch_bounds__(256) kernelA(
    const float* __restrict__ x, const float* __restrict__ Wx,
    const float* __restrict__ bx, const float* __restrict__ We,
    const float* __restrict__ be, const float* __restrict__ Wih,
    const float* __restrict__ bih, const float* __restrict__ bhh) {
    extern __shared__ float sm[];
    float* As = sm;
    float* Ws = sm + 128 * 128;
    const int bt = blockIdx.x, t = blockIdx.y, c = blockIdx.z;
    const long rg0 = ((long)(c * T_ + t) * B_ + bt * 128);
    const int tc = threadIdx.x & 15, tr = threadIdx.x >> 4;

    load_tile(As, x + rg0 * F_, F_);
    load_tile(Ws, Wx + (size_t)c * F_ * HX_, HX_);
    __syncthreads();

    float acc[8][8];
    zero_acc(acc);
    gemm128(As, Ws, acc);      // x_phi (pre-bias)
    __syncthreads();
    // write x_phi (+bx) back into As
#pragma unroll
    for (int i = 0; i < 8; ++i)
#pragma unroll
        for (int j = 0; j < 8; ++j)
            As[(tr * 8 + i) * 128 + tc * 8 + j] = acc[i][j] + bx[c * HX_ + tc * 8 + j];
    __syncthreads();

    // PE = x_phi @ We_x + be   (We rows 0..127, contiguous block)
    load_tile(Ws, We + (size_t)c * 384 * EH_, EH_);
    __syncthreads();
    zero_acc(acc);
    gemm128(As, Ws, acc);
#pragma unroll
    for (int i = 0; i < 8; ++i)
#pragma unroll
        for (int j = 0; j < 8; ++j)
            g_PE[(rg0 + tr * 8 + i) * EH_ + tc * 8 + j] =
                acc[i][j] + be[c * EH_ + tc * 8 + j];

    // PI = x_phi @ Wih_x + bih + bhh   (Wih rows 0..127, two 128-col halves)
    for (int half = 0; half < 2; ++half) {
        __syncthreads();
        load_tile(Ws, Wih + half * 128, H_);
        __syncthreads();
        zero_acc(acc);
        gemm128(As, Ws, acc);
#pragma unroll
        for (int i = 0; i < 8; ++i)
#pragma unroll
            for (int j = 0; j < 8; ++j) {
                const int n = half * 128 + tc * 8 + j;
                g_PI[(rg0 + tr * 8 + i) * H_ + n] = acc[i][j] + bih[n] + bhh[n];
            }
    }
}

// ---------------------------------------------------------------------------
// Skinny GEMM for the recurrence: acc[r] += a_s[r][:] @ W[:,n]
// 256 threads; P = 256/N k-partitions per column; caller reduces partials.
// a_s: smem [R][K] row-major; W: global [K][N] row-major (L2-resident).
// ---------------------------------------------------------------------------
template <int K, int N>
__device__ __forceinline__ void mm_acc(const float* __restrict__ Wg, const int ldw,
                                       const float* __restrict__ a_s, const int R,
                                       float* __restrict__ acc) {
    constexpr int P = 256 / N;
    constexpr int Ks = K / P;
    const int n = threadIdx.x % N;
    const int p = threadIdx.x / N;
    const float* w = Wg + (size_t)(p * Ks) * ldw + n;
    const float* a0 = a_s + p * Ks;
#pragma unroll 2
    for (int k = 0; k < Ks; k += 4) {
        const float w0 = w[(size_t)(k + 0) * ldw];
        const float w1 = w[(size_t)(k + 1) * ldw];
        const float w2 = w[(size_t)(k + 2) * ldw];
        const float w3 = w[(size_t)(k + 3) * ldw];
#pragma unroll
        for (int r = 0; r < RMAX_; ++r) {
            if (r < R) {
                const float4 a = *reinterpret_cast<const float4*>(a0 + r * K + k);
                acc[r] = fmaf(a.x, w0, fmaf(a.y, w1,
                          fmaf(a.z, w2, fmaf(a.w, w3, acc[r]))));
            }
        }
    }
}

// ---------------------------------------------------------------------------
// Kernel B: the recurrence. grid (NB_ per channel, C), 256 threads.
// Per step: e = PE + h@We_h; z = e@Wqm+bqm; zp = z@Wzp+bzp;
//           h' = tanh(PI + zp@Wih_z + h@Whh). Stores Hs (pre-update h), Zs.
// ---------------------------------------------------------------------------
__global__ void __launch_bounds__(256) kernelB(
    const float* __restrict__ We, const float* __restrict__ Wqm,
    const float* __restrict__ bqm, const float* __restrict__ Wzp,
    const float* __restrict__ bzp, const float* __restrict__ Wih,
    const float* __restrict__ Whh, const float* __restrict__ h0) {
    __shared__ __align__(16) float hs[RMAX_ * H_];
    __shared__ __align__(16) float es[RMAX_ * EH_];
    __shared__ __align__(16) float zs[RMAX_ * L_];
    __shared__ __align__(16) float zps[RMAX_ * HZ_];
    __shared__ __align__(16) float scr[4 * RMAX_ * 64];  // max P*R*N = 2816 floats

    const int c = blockIdx.y;
    const int r0 = (blockIdx.x * B_) / NB_;
    const int r1 = ((blockIdx.x + 1) * B_) / NB_;
    const int R = r1 - r0;
    const int tid = threadIdx.x;

    for (int idx = tid; idx < R * H_; idx += 256)
        hs[idx] = h0[(size_t)(c * B_ + r0) * H_ + idx];
    __syncthreads();

    const float* We_h  = We + (size_t)c * 384 * EH_ + 128 * EH_;  // rows 128..383
    const float* Wqm_c = Wqm + (size_t)c * EH_ * L_;
    const float* Wih_z = Wih + 128 * H_;                          // rows 128..255

    float acc[RMAX_];

    for (int t = 0; t < T_; ++t) {
        const long rg0 = ((long)(c * T_ + t) * B_ + r0);

        // ---- G1: e = PE + h @ We_h   (K=256, N=128, P=2)
#pragma unroll
        for (int r = 0; r < RMAX_; ++r) acc[r] = 0.f;
        mm_acc<256, 128>(We_h, 128, hs, R, acc);
        {
            const int n = tid & 127, p = tid >> 7;
            for (int r = 0; r < R; ++r) scr[(p * R + r) * 128 + n] = acc[r];
        }
        __syncthreads();
        for (int idx = tid; idx < R * EH_; idx += 256) {
            const int r = idx >> 7, n = idx & 127;
            es[idx] = scr[r * 128 + n] + scr[(R + r) * 128 + n] +
                      g_PE[(rg0 + r) * EH_ + n];
        }
        for (int idx = tid; idx < R * H_; idx += 256)  // Hs[t] = h (pre-update)
            g_Hs[rg0 * H_ + idx] = hs[idx];
        __syncthreads();

        // ---- G2: z = e @ Wqm + bqm   (K=128, N=64, P=4)
#pragma unroll
        for (int r = 0; r < RMAX_; ++r) acc[r] = 0.f;
        mm_acc<128, 64>(Wqm_c, 64, es, R, acc);
        {
            const int n = tid & 63, p = tid >> 6;
            for (int r = 0; r < R; ++r) scr[(p * R + r) * 64 + n] = acc[r];
        }
        __syncthreads();
        for (int idx = tid; idx < R * L_; idx += 256) {
            const int r = idx >> 6, n = idx & 63;
            zs[idx] = scr[r * 64 + n] + scr[(R + r) * 64 + n] +
                      scr[(2 * R + r) * 64 + n] + scr[(3 * R + r) * 64 + n] +
                      bqm[c * L_ + n];
        }
        __syncthreads();

        // ---- G3: zp = z @ Wzp + bzp   (K=64, N=128, P=2)
#pragma unroll
        for (int r = 0; r < RMAX_; ++r) acc[r] = 0.f;
        mm_acc<64, 128>(Wzp, 128, zs, R, acc);
        {
            const int n = tid & 127, p = tid >> 7;
            for (int r = 0; r < R; ++r) scr[(p * R + r) * 128 + n] = acc[r];
        }
        __syncthreads();
        for (int idx = tid; idx < R * HZ_; idx += 256) {
            const int r = idx >> 7, n = idx & 127;
            zps[idx] = scr[r * 128 + n] + scr[(R + r) * 128 + n] + bzp[n];
        }
        __syncthreads();

        // ---- store Zs + G4: h' = tanh(PI + zp@Wih_z + h@Whh)  (N=256, P=1)
        for (int idx = tid; idx < R * HZ_; idx += 256)
            g_Zs[rg0 * HZ_ + idx] = zps[idx];
#pragma unroll
        for (int r = 0; r < RMAX_; ++r) acc[r] = 0.f;
        mm_acc<128, 256>(Wih_z, 256, zps, R, acc);
        mm_acc<256, 256>(Whh, 256, hs, R, acc);
        {
            const int n = tid;  // 0..255
            float v[RMAX_];
#pragma unroll
            for (int r = 0; r < RMAX_; ++r)
                if (r < R) v[r] = tanhf(acc[r] + g_PI[(rg0 + r) * H_ + n]);
            __syncthreads();  // everyone done reading hs
#pragma unroll
            for (int r = 0; r < RMAX_; ++r)
                if (r < R) hs[r * H_ + n] = v[r];
        }
        __syncthreads();
    }
}

// ---------------------------------------------------------------------------
// Kernel C: d = Zs@Wd_z + Hs@Wd_h + bd ; out = d@Wpm + bpm
// grid (4 btiles, T, C), 256 threads, 128KB dynamic smem
// ---------------------------------------------------------------------------
__global__ void __launch_bounds__(256) kernelC(
    const float* __restrict__ Wd, const float* __restrict__ bd,
    const float* __restrict__ Wpm, const float* __restrict__ bpm,
    float* __restrict__ out) {
    extern __shared__ float sm[];
    float* As = sm;
    float* Ws = sm + 128 * 128;
    const int bt = blockIdx.x, t = blockIdx.y, c = blockIdx.z;
    const long rg0 = ((long)(c * T_ + t) * B_ + bt * 128);
    const int tc = threadIdx.x & 15, tr = threadIdx.x >> 4;

    float acc[8][8];
    zero_acc(acc);

    load_tile(As, g_Zs + rg0 * HZ_, HZ_);
    load_tile(Ws, Wd + (size_t)c * 384 * EH_, EH_);  // rows 0..127 (z part)
    __syncthreads();
    gemm128(As, Ws, acc);
    __syncthreads();

    load_tile(As, g_Hs + rg0 * H_, H_);              // h cols 0..127
    load_tile(Ws, Wd + (size_t)c * 384 * EH_ + 128 * EH_, EH_);
    __syncthreads();
    gemm128(As, Ws, acc);
    __syncthreads();

    load_tile(As, g_Hs + rg0 * H_ + 128, H_);        // h cols 128..255
    load_tile(Ws, Wd + (size_t)c * 384 * EH_ + 256 * EH_, EH_);
    __syncthreads();
    gemm128(As, Ws, acc);
    __syncthreads();

    // d (+bd) into As
#pragma unroll
    for (int i = 0; i < 8; ++i)
#pragma unroll
        for (int j = 0; j < 8; ++j)
            As[(tr * 8 + i) * 128 + tc * 8 + j] = acc[i][j] + bd[c * EH_ + tc * 8 + j];
    load_tile(Ws, Wpm + (size_t)c * EH_ * F_, F_);
    __syncthreads();

    zero_acc(acc);
    gemm128(As, Ws, acc);
#pragma unroll
    for (int i = 0; i < 8; ++i)
#pragma unroll
        for (int j = 0; j < 8; ++j)
            out[(rg0 + tr * 8 + i) * F_ + tc * 8 + j] =
                acc[i][j] + bpm[c * F_ + tc * 8 + j];
}

// ---------------------------------------------------------------------------
extern "C" void kernel_launch(void* const* d_in, const int* in_sizes, int n_in,
                              void* d_out, int out_size) {
    (void)in_sizes; (void)n_in; (void)out_size;
    const float* x        = (const float*)d_in[0];
    const float* phi_x_W  = (const float*)d_in[1];
    const float* phi_x_b  = (const float*)d_in[2];
    const float* enc_W    = (const float*)d_in[3];
    const float* enc_b    = (const float*)d_in[4];
    const float* enc_mu_W = (const float*)d_in[5];
    const float* enc_mu_b = (const float*)d_in[6];
    const float* phi_z_W  = (const float*)d_in[7];
    const float* phi_z_b  = (const float*)d_in[8];
    const float* dec_W    = (const float*)d_in[9];
    const float* dec_b    = (const float*)d_in[10];
    const float* dec_mu_W = (const float*)d_in[11];
    const float* dec_mu_b = (const float*)d_in[12];
    const float* rnn_Wih  = (const float*)d_in[13];
    const float* rnn_Whh  = (const float*)d_in[14];
    const float* rnn_bih  = (const float*)d_in[15];
    const float* rnn_bhh  = (const float*)d_in[16];
    const float* h0       = (const float*)d_in[17];
    float* out = (float*)d_out;

    const size_t smem = 2 * 128 * 128 * sizeof(float);  // 128 KB
    cudaFuncSetAttribute(kernelA, cudaFuncAttributeMaxDynamicSharedMemorySize, (int)smem);
    cudaFuncSetAttribute(kernelC, cudaFuncAttributeMaxDynamicSharedMemorySize, (int)smem);

    kernelA<<<dim3(4, T_, C_), 256, smem>>>(x, phi_x_W, phi_x_b, enc_W, enc_b,
                                            rnn_Wih, rnn_bih, rnn_bhh);
    kernelB<<<dim3(NB_, C_), 256>>>(enc_W, enc_mu_W, enc_mu_b, phi_z_W, phi_z_b,
                                    rnn_Wih, rnn_Whh, h0);
    kernelC<<<dim3(4, T_, C_), 256, smem>>>(dec_W, dec_b, dec_mu_W, dec_mu_b, out);
}

// round 3
// speedup vs baseline: 1.5263x; 1.5263x over previous
#include <cuda_runtime.h>
#include <math.h>

// Problem dims
#define C_   3
#define T_   100
#define B_   512
#define F_   128
#define HX_  128
#define HZ_  128
#define H_   256
#define EH_  128
#define L_   64

#define NB_   48   // CTAs per channel in sequential kernel
#define RMAX_ 11   // rows per CTA (overlapping coverage of 512)

// Scratch (device globals: allocations are forbidden)
__device__ float g_PE[(size_t)C_ * T_ * B_ * EH_];  // x_phi@We_x + be
__device__ float g_PI[(size_t)C_ * T_ * B_ * H_];   // x_phi@Wih_x + bih + bhh
__device__ float g_Hs[(size_t)C_ * T_ * B_ * H_];   // h at step input
__device__ float g_Zs[(size_t)C_ * T_ * B_ * HZ_];  // z_phi per step

// ===========================================================================
// Parallel GEMM machinery (kernels A and C)
// 128x128 output tile, 256 threads, 8x8 acc per thread.
// Ws holds a 64-row k-slab of the weight tile (96KB total smem -> 2 CTA/SM).
// ===========================================================================
__device__ __forceinline__ void gemm64(const float* __restrict__ As,
                                       const float* __restrict__ Ws,
                                       int k0, float acc[8][8]) {
    const int tc = threadIdx.x & 15;
    const int tr = threadIdx.x >> 4;
    const float* ap = As + tr * 8 * 128 + k0;
    const float* bp = Ws + tc * 8;
#pragma unroll 4
    for (int k = 0; k < 64; ++k) {
        const float4 b0 = *reinterpret_cast<const float4*>(bp + k * 128);
        const float4 b1 = *reinterpret_cast<const float4*>(bp + k * 128 + 4);
        float a[8];
#pragma unroll
        for (int i = 0; i < 8; ++i) a[i] = ap[i * 128 + k];
        const float bv[8] = {b0.x, b0.y, b0.z, b0.w, b1.x, b1.y, b1.z, b1.w};
#pragma unroll
        for (int i = 0; i < 8; ++i)
#pragma unroll
            for (int j = 0; j < 8; ++j)
                acc[i][j] = fmaf(a[i], bv[j], acc[i][j]);
    }
}

// Load a 128x128 fp32 tile (row stride ld) into smem
__device__ __forceinline__ void load_tile(float* dst, const float* __restrict__ src,
                                          int ld) {
    for (int idx = threadIdx.x; idx < 128 * 32; idx += 256) {
        const int r = idx >> 5;
        const int c4 = idx & 31;
        reinterpret_cast<float4*>(dst)[(r << 5) + c4] =
            *reinterpret_cast<const float4*>(src + (size_t)r * ld + (c4 << 2));
    }
}

// Load a 64x128 fp32 slab (row stride ld) into smem
__device__ __forceinline__ void load_half(float* dst, const float* __restrict__ src,
                                          int ld) {
    for (int idx = threadIdx.x; idx < 64 * 32; idx += 256) {
        const int r = idx >> 5;
        const int c4 = idx & 31;
        reinterpret_cast<float4*>(dst)[(r << 5) + c4] =
            *reinterpret_cast<const float4*>(src + (size_t)r * ld + (c4 << 2));
    }
}

__device__ __forceinline__ void zero_acc(float acc[8][8]) {
#pragma unroll
    for (int i = 0; i < 8; ++i)
#pragma unroll
        for (int j = 0; j < 8; ++j) acc[i][j] = 0.f;
}

// run a full 128-deep GEMM as two 64-row slabs streamed through Ws
__device__ __forceinline__ void gemm128_slabs(const float* As, float* Ws,
                                              const float* __restrict__ W,
                                              int ldw, float acc[8][8]) {
#pragma unroll
    for (int h = 0; h < 2; ++h) {
        load_half(Ws, W + (size_t)(h * 64) * ldw, ldw);
        __syncthreads();
        gemm64(As, Ws, h * 64, acc);
        __syncthreads();
    }
}

// ---------------------------------------------------------------------------
// Kernel A: PE = (x@Wx+bx)@We_x + be ;  PI = (x@Wx+bx)@Wih_x + bih + bhh
// grid (4 btiles, T, C), 256 threads, 96KB dynamic smem
// ---------------------------------------------------------------------------
__global__ void __launch_bounds__(256, 2) kernelA(
    const float* __restrict__ x, const float* __restrict__ Wx,
    const float* __restrict__ bx, const float* __restrict__ We,
    const float* __restrict__ be, const float* __restrict__ Wih,
    const float* __restrict__ bih, const float* __restrict__ bhh) {
    extern __shared__ float sm[];
    float* As = sm;                // 128x128
    float* Ws = sm + 128 * 128;    // 64x128 slab
    const int bt = blockIdx.x, t = blockIdx.y, c = blockIdx.z;
    const long rg0 = ((long)(c * T_ + t) * B_ + bt * 128);
    const int tc = threadIdx.x & 15, tr = threadIdx.x >> 4;

    load_tile(As, x + rg0 * F_, F_);

    float acc[8][8];
    zero_acc(acc);
    gemm128_slabs(As, Ws, Wx + (size_t)c * F_ * HX_, HX_, acc);  // x_phi

    // write x_phi (+bx) back into As  (safe: trailing sync above; next sync
    // inside gemm128_slabs happens before any thread reads As again)
#pragma unroll
    for (int i = 0; i < 8; ++i)
#pragma unroll
        for (int j = 0; j < 8; ++j)
            As[(tr * 8 + i) * 128 + tc * 8 + j] = acc[i][j] + bx[c * HX_ + tc * 8 + j];

    // PE = x_phi @ We_x + be   (We rows 0..127)
    zero_acc(acc);
    gemm128_slabs(As, Ws, We + (size_t)c * 384 * EH_, EH_, acc);
#pragma unroll
    for (int i = 0; i < 8; ++i)
#pragma unroll
        for (int j = 0; j < 8; ++j)
            g_PE[(rg0 + tr * 8 + i) * EH_ + tc * 8 + j] =
                acc[i][j] + be[c * EH_ + tc * 8 + j];

    // PI = x_phi @ Wih_x + bih + bhh   (Wih rows 0..127, two 128-col halves)
#pragma unroll
    for (int half = 0; half < 2; ++half) {
        zero_acc(acc);
        gemm128_slabs(As, Ws, Wih + half * 128, H_, acc);
#pragma unroll
        for (int i = 0; i < 8; ++i)
#pragma unroll
            for (int j = 0; j < 8; ++j) {
                const int n = half * 128 + tc * 8 + j;
                g_PI[(rg0 + tr * 8 + i) * H_ + n] = acc[i][j] + bih[n] + bhh[n];
            }
    }
}

// ===========================================================================
// Kernel B: the recurrence.
// Each thread owns a float4 of output columns; k is partitioned P ways;
// partials reduced through smem scratch. Weights streamed from L2 with
// double-buffered LDG.128; activations broadcast from smem as float4.
// ===========================================================================
template <int K, int N>
__device__ __forceinline__ void mm4(const float* __restrict__ Wg,
                                    const float* __restrict__ a_s,
                                    float4 acc[RMAX_]) {
    constexpr int G = N / 4;      // thread groups (one per 4 columns)
    constexpr int P = 256 / G;    // k partitions
    constexpr int Ks = K / P;
    const int g = threadIdx.x % G;
    const int p = threadIdx.x / G;
    const float4* wp = reinterpret_cast<const float4*>(Wg) + (size_t)(p * Ks) * G + g;
    const float* ap = a_s + p * Ks;

    float4 w0 = wp[0 * G], w1 = wp[1 * G], w2 = wp[2 * G], w3 = wp[3 * G];
#pragma unroll 1
    for (int k = 0; k < Ks; k += 4) {
        float4 n0, n1, n2, n3;
        if (k + 4 < Ks) {
            n0 = wp[(k + 4) * G];
            n1 = wp[(k + 5) * G];
            n2 = wp[(k + 6) * G];
            n3 = wp[(k + 7) * G];
        }
#pragma unroll
        for (int r = 0; r < RMAX_; ++r) {
            const float4 a = *reinterpret_cast<const float4*>(ap + r * K + k);
            acc[r].x = fmaf(a.x, w0.x, acc[r].x);
            acc[r].y = fmaf(a.x, w0.y, acc[r].y);
            acc[r].z = fmaf(a.x, w0.z, acc[r].z);
            acc[r].w = fmaf(a.x, w0.w, acc[r].w);
            acc[r].x = fmaf(a.y, w1.x, acc[r].x);
            acc[r].y = fmaf(a.y, w1.y, acc[r].y);
            acc[r].z = fmaf(a.y, w1.z, acc[r].z);
            acc[r].w = fmaf(a.y, w1.w, acc[r].w);
            acc[r].x = fmaf(a.z, w2.x, acc[r].x);
            acc[r].y = fmaf(a.z, w2.y, acc[r].y);
            acc[r].z = fmaf(a.z, w2.z, acc[r].z);
            acc[r].w = fmaf(a.z, w2.w, acc[r].w);
            acc[r].x = fmaf(a.w, w3.x, acc[r].x);
            acc[r].y = fmaf(a.w, w3.y, acc[r].y);
            acc[r].z = fmaf(a.w, w3.z, acc[r].z);
            acc[r].w = fmaf(a.w, w3.w, acc[r].w);
        }
        w0 = n0; w1 = n1; w2 = n2; w3 = n3;
    }
}

template <int N>
__device__ __forceinline__ void store_scr(float* __restrict__ scr,
                                          const float4 acc[RMAX_]) {
    const int g = threadIdx.x % (N / 4);
    const int p = threadIdx.x / (N / 4);
#pragma unroll
    for (int r = 0; r < RMAX_; ++r)
        *reinterpret_cast<float4*>(scr + (size_t)(p * RMAX_ + r) * N + 4 * g) = acc[r];
}

__device__ __forceinline__ void zero4(float4 acc[RMAX_]) {
#pragma unroll
    for (int r = 0; r < RMAX_; ++r) acc[r] = make_float4(0.f, 0.f, 0.f, 0.f);
}

__global__ void __launch_bounds__(256) kernelB(
    const float* __restrict__ We, const float* __restrict__ Wqm,
    const float* __restrict__ bqm, const float* __restrict__ Wzp,
    const float* __restrict__ bzp, const float* __restrict__ Wih,
    const float* __restrict__ Whh, const float* __restrict__ h0) {
    __shared__ __align__(16) float hs[RMAX_ * H_];
    __shared__ __align__(16) float es[RMAX_ * EH_];
    __shared__ __align__(16) float zs[RMAX_ * L_];
    __shared__ __align__(16) float zps[RMAX_ * HZ_];
    __shared__ __align__(16) float scr[RMAX_ * 1024];  // P*N == 1024 for all mm4

    const int c = blockIdx.y;
    // overlapping coverage: 48 CTAs x 11 rows >= 512; duplicated rows compute
    // bit-identical values, duplicate global stores are benign.
    const int r0 = (blockIdx.x * (B_ - RMAX_)) / (NB_ - 1);
    const int tid = threadIdx.x;

    for (int idx = tid; idx < RMAX_ * H_; idx += 256)
        hs[idx] = h0[(size_t)(c * B_ + r0) * H_ + idx];
    __syncthreads();

    const float* We_h  = We + (size_t)c * 384 * EH_ + 128 * EH_;  // rows 128..383
    const float* Wqm_c = Wqm + (size_t)c * EH_ * L_;
    const float* Wih_z = Wih + 128 * H_;                          // rows 128..255
    const float* bqm_c = bqm + c * L_;

    float4 acc[RMAX_];

    long rg0 = (long)c * T_ * B_ + r0;
    for (int t = 0; t < T_; ++t, rg0 += B_) {
        // ---- G1: e = PE + h @ We_h   (K=256, N=128, P=8)
        zero4(acc);
        mm4<256, 128>(We_h, hs, acc);
        store_scr<128>(scr, acc);
        // store Hs[t] = h (pre-update) while partials land
        for (int idx = tid; idx < RMAX_ * H_; idx += 256)
            g_Hs[rg0 * H_ + idx] = hs[idx];
        __syncthreads();
        for (int idx = tid; idx < RMAX_ * EH_; idx += 256) {
            const int r = idx >> 7, n = idx & 127;
            float s = g_PE[(rg0 + r) * EH_ + n];
#pragma unroll
            for (int p = 0; p < 8; ++p) s += scr[(size_t)(p * RMAX_ + r) * 128 + n];
            es[idx] = s;
        }
        __syncthreads();

        // ---- G2: z = e @ Wqm + bqm   (K=128, N=64, P=16)
        zero4(acc);
        mm4<128, 64>(Wqm_c, es, acc);
        store_scr<64>(scr, acc);
        __syncthreads();
        for (int idx = tid; idx < RMAX_ * L_; idx += 256) {
            const int r = idx >> 6, n = idx & 63;
            float s = bqm_c[n];
#pragma unroll
            for (int p = 0; p < 16; ++p) s += scr[(size_t)(p * RMAX_ + r) * 64 + n];
            zs[idx] = s;
        }
        __syncthreads();

        // ---- G3: zp = z @ Wzp + bzp   (K=64, N=128, P=8)
        zero4(acc);
        mm4<64, 128>(Wzp, zs, acc);
        store_scr<128>(scr, acc);
        __syncthreads();
        for (int idx = tid; idx < RMAX_ * HZ_; idx += 256) {
            const int r = idx >> 7, n = idx & 127;
            float s = bzp[n];
#pragma unroll
            for (int p = 0; p < 8; ++p) s += scr[(size_t)(p * RMAX_ + r) * 128 + n];
            zps[idx] = s;
            g_Zs[rg0 * HZ_ + idx] = s;
        }
        __syncthreads();

        // ---- G4: h' = tanh(PI + zp@Wih_z + h@Whh)   (N=256, P=4)
        zero4(acc);
        mm4<128, 256>(Wih_z, zps, acc);
        mm4<256, 256>(Whh, hs, acc);
        store_scr<256>(scr, acc);
        __syncthreads();
        for (int idx = tid; idx < RMAX_ * H_; idx += 256) {
            const int r = idx >> 8, n = idx & 255;
            float s = g_PI[(rg0 + r) * H_ + n];
#pragma unroll
            for (int p = 0; p < 4; ++p) s += scr[(size_t)(p * RMAX_ + r) * 256 + n];
            hs[idx] = tanhf(s);
        }
        __syncthreads();
    }
}

// ---------------------------------------------------------------------------
// Kernel C: d = Zs@Wd_z + Hs@Wd_h + bd ; out = d@Wpm + bpm
// grid (4 btiles, T, C), 256 threads, 96KB dynamic smem
// ---------------------------------------------------------------------------
__global__ void __launch_bounds__(256, 2) kernelC(
    const float* __restrict__ Wd, const float* __restrict__ bd,
    const float* __restrict__ Wpm, const float* __restrict__ bpm,
    float* __restrict__ out) {
    extern __shared__ float sm[];
    float* As = sm;
    float* Ws = sm + 128 * 128;
    const int bt = blockIdx.x, t = blockIdx.y, c = blockIdx.z;
    const long rg0 = ((long)(c * T_ + t) * B_ + bt * 128);
    const int tc = threadIdx.x & 15, tr = threadIdx.x >> 4;
    const float* Wd_c = Wd + (size_t)c * 384 * EH_;

    float acc[8][8];
    zero_acc(acc);

    // tile 0: z_phi part (Wd rows 0..127)
    load_tile(As, g_Zs + rg0 * HZ_, HZ_);
    gemm128_slabs(As, Ws, Wd_c, EH_, acc);
    // tile 1: h cols 0..127 (Wd rows 128..255)
    load_tile(As, g_Hs + rg0 * H_, H_);
    gemm128_slabs(As, Ws, Wd_c + 128 * EH_, EH_, acc);
    // tile 2: h cols 128..255 (Wd rows 256..383)
    load_tile(As, g_Hs + rg0 * H_ + 128, H_);
    gemm128_slabs(As, Ws, Wd_c + 256 * EH_, EH_, acc);

    // d (+bd) into As
#pragma unroll
    for (int i = 0; i < 8; ++i)
#pragma unroll
        for (int j = 0; j < 8; ++j)
            As[(tr * 8 + i) * 128 + tc * 8 + j] = acc[i][j] + bd[c * EH_ + tc * 8 + j];

    zero_acc(acc);
    gemm128_slabs(As, Ws, Wpm + (size_t)c * EH_ * F_, F_, acc);
#pragma unroll
    for (int i = 0; i < 8; ++i)
#pragma unroll
        for (int j = 0; j < 8; ++j)
            out[(rg0 + tr * 8 + i) * F_ + tc * 8 + j] =
                acc[i][j] + bpm[c * F_ + tc * 8 + j];
}

// ---------------------------------------------------------------------------
extern "C" void kernel_launch(void* const* d_in, const int* in_sizes, int n_in,
                              void* d_out, int out_size) {
    (void)in_sizes; (void)n_in; (void)out_size;
    const float* x        = (const float*)d_in[0];
    const float* phi_x_W  = (const float*)d_in[1];
    const float* phi_x_b  = (const float*)d_in[2];
    const float* enc_W    = (const float*)d_in[3];
    const float* enc_b    = (const float*)d_in[4];
    const float* enc_mu_W = (const float*)d_in[5];
    const float* enc_mu_b = (const float*)d_in[6];
    const float* phi_z_W  = (const float*)d_in[7];
    const float* phi_z_b  = (const float*)d_in[8];
    const float* dec_W    = (const float*)d_in[9];
    const float* dec_b    = (const float*)d_in[10];
    const float* dec_mu_W = (const float*)d_in[11];
    const float* dec_mu_b = (const float*)d_in[12];
    const float* rnn_Wih  = (const float*)d_in[13];
    const float* rnn_Whh  = (const float*)d_in[14];
    const float* rnn_bih  = (const float*)d_in[15];
    const float* rnn_bhh  = (const float*)d_in[16];
    const float* h0       = (const float*)d_in[17];
    float* out = (float*)d_out;

    const size_t smem = (128 * 128 + 64 * 128) * sizeof(float);  // 96 KB
    cudaFuncSetAttribute(kernelA, cudaFuncAttributeMaxDynamicSharedMemorySize, (int)smem);
    cudaFuncSetAttribute(kernelC, cudaFuncAttributeMaxDynamicSharedMemorySize, (int)smem);

    kernelA<<<dim3(4, T_, C_), 256, smem>>>(x, phi_x_W, phi_x_b, enc_W, enc_b,
                                            rnn_Wih, rnn_bih, rnn_bhh);
    kernelB<<<dim3(NB_, C_), 256>>>(enc_W, enc_mu_W, enc_mu_b, phi_z_W, phi_z_b,
                                    rnn_Wih, rnn_Whh, h0);
    kernelC<<<dim3(4, T_, C_), 256, smem>>>(dec_W, dec_b, dec_mu_W, dec_mu_b, out);
}

// round 4
// speedup vs baseline: 1.8304x; 1.1993x over previous
#include <cuda_runtime.h>
#include <math.h>

// Problem dims
#define C_   3
#define T_   100
#define B_   512
#define F_   128
#define HX_  128
#define HZ_  128
#define H_   256
#define EH_  128
#define L_   64

#define NB_   48   // CTAs per channel in sequential kernel
#define RMAX_ 11   // rows per CTA (overlapping coverage of 512)

// ---- big activations scratch ----
__device__ float g_PEq[(size_t)C_ * T_ * B_ * L_];  // x_phi@Weq + beq  (feeds z)
__device__ float g_PI[(size_t)C_ * T_ * B_ * H_];   // x_phi@Wih_x + bih+bhh+bihz
__device__ float g_Hs[(size_t)C_ * T_ * B_ * H_];   // h at step input
__device__ float g_Zs[(size_t)C_ * T_ * B_ * L_];   // z per step

// ---- folded weights (computed on-device each run; tiny) ----
__device__ float g_Weq[C_ * HX_ * L_];    // We_x @ Wqm            [128,64]/ch
__device__ float g_beq[C_ * L_];          // be@Wqm + bqm
__device__ float g_Wcomb[C_ * H_ * L_];   // We_h @ Wqm            [256,64]/ch
__device__ float g_Wihz[L_ * H_];         // Wzp @ Wih_z           [64,256]
__device__ float g_bihz[H_];              // bzp @ Wih_z
__device__ float g_Wdz[C_ * L_ * EH_];    // Wzp @ Wd_z            [64,128]/ch
__device__ float g_bdz[C_ * EH_];         // bzp@Wd_z + bd
__device__ float g_Wzo[C_ * L_ * F_];     // Wdz @ Wpm             [64,128]/ch
__device__ float g_Who[C_ * H_ * F_];     // Wd_h @ Wpm            [256,128]/ch
__device__ float g_bo[C_ * F_];           // bdz@Wpm + bpm

// ===========================================================================
// small generic GEMM for weight folding (one CTA per task, K=128 always)
// ===========================================================================
__device__ __forceinline__ void small_gemm(const float* __restrict__ A, int lda,
                                           const float* __restrict__ Bm, int ldb,
                                           float* __restrict__ out, int M, int N,
                                           const float* __restrict__ addv) {
    for (int idx = threadIdx.x; idx < M * N; idx += 256) {
        const int m = idx / N, n = idx % N;
        float s = addv ? addv[n] : 0.f;
        const float* a = A + (size_t)m * lda;
        const float* b = Bm + n;
#pragma unroll 4
        for (int k = 0; k < 128; ++k) s = fmaf(a[k], b[(size_t)k * ldb], s);
        out[idx] = s;
    }
}

// fold stage 1: products of raw inputs (29 CTAs)
__global__ void __launch_bounds__(256) kernelF1(
    const float* __restrict__ We, const float* __restrict__ be,
    const float* __restrict__ Wqm, const float* __restrict__ bqm,
    const float* __restrict__ Wzp, const float* __restrict__ bzp,
    const float* __restrict__ Wd, const float* __restrict__ bd,
    const float* __restrict__ Wih) {
    const int t = blockIdx.x;
    if (t < 6) {                       // Weq blocks (M=64)
        const int c = t >> 1, rb = t & 1;
        small_gemm(We + (size_t)c * 384 * EH_ + rb * 64 * EH_, EH_,
                   Wqm + (size_t)c * EH_ * L_, L_,
                   g_Weq + c * HX_ * L_ + rb * 64 * L_, 64, L_, nullptr);
    } else if (t < 18) {               // Wcomb blocks
        const int u = t - 6, c = u >> 2, rb = u & 3;
        small_gemm(We + (size_t)c * 384 * EH_ + (128 + rb * 64) * EH_, EH_,
                   Wqm + (size_t)c * EH_ * L_, L_,
                   g_Wcomb + c * H_ * L_ + rb * 64 * L_, 64, L_, nullptr);
    } else if (t < 21) {               // Wdz = Wzp @ Wd_z
        const int c = t - 18;
        small_gemm(Wzp, HZ_, Wd + (size_t)c * 384 * EH_, EH_,
                   g_Wdz + c * L_ * EH_, L_, EH_, nullptr);
    } else if (t == 21) {              // Wihz = Wzp @ Wih_z
        small_gemm(Wzp, HZ_, Wih + 128 * H_, H_, g_Wihz, L_, H_, nullptr);
    } else if (t < 25) {               // beq = be@Wqm + bqm
        const int c = t - 22;
        small_gemm(be + c * EH_, EH_, Wqm + (size_t)c * EH_ * L_, L_,
                   g_beq + c * L_, 1, L_, bqm + c * L_);
    } else if (t < 28) {               // bdz = bzp@Wd_z + bd
        const int c = t - 25;
        small_gemm(bzp, HZ_, Wd + (size_t)c * 384 * EH_, EH_,
                   g_bdz + c * EH_, 1, EH_, bd + c * EH_);
    } else {                           // bihz = bzp@Wih_z
        small_gemm(bzp, HZ_, Wih + 128 * H_, H_, g_bihz, 1, H_, nullptr);
    }
}

// fold stage 2: products involving fold-1 outputs (18 CTAs)
__global__ void __launch_bounds__(256) kernelF2(
    const float* __restrict__ Wd, const float* __restrict__ Wpm,
    const float* __restrict__ bpm) {
    const int t = blockIdx.x;
    if (t < 3) {                       // Wzo = Wdz @ Wpm
        const int c = t;
        small_gemm(g_Wdz + c * L_ * EH_, EH_, Wpm + (size_t)c * EH_ * F_, F_,
                   g_Wzo + c * L_ * F_, L_, F_, nullptr);
    } else if (t < 15) {               // Who = Wd_h @ Wpm
        const int u = t - 3, c = u >> 2, rb = u & 3;
        small_gemm(Wd + (size_t)c * 384 * EH_ + (128 + rb * 64) * EH_, EH_,
                   Wpm + (size_t)c * EH_ * F_, F_,
                   g_Who + c * H_ * F_ + rb * 64 * F_, 64, F_, nullptr);
    } else {                           // bo = bdz@Wpm + bpm
        const int c = t - 15;
        small_gemm(g_bdz + c * EH_, EH_, Wpm + (size_t)c * EH_ * F_, F_,
                   g_bo + c * F_, 1, F_, bpm + c * F_);
    }
}

// ===========================================================================
// Parallel GEMM machinery (kernels A and C)
// ===========================================================================
__device__ __forceinline__ void gemm64(const float* __restrict__ As,
                                       const float* __restrict__ Ws,
                                       int k0, float acc[8][8]) {
    const int tc = threadIdx.x & 15;
    const int tr = threadIdx.x >> 4;
    const float* ap = As + tr * 8 * 128 + k0;
    const float* bp = Ws + tc * 8;
#pragma unroll 4
    for (int k = 0; k < 64; ++k) {
        const float4 b0 = *reinterpret_cast<const float4*>(bp + k * 128);
        const float4 b1 = *reinterpret_cast<const float4*>(bp + k * 128 + 4);
        float a[8];
#pragma unroll
        for (int i = 0; i < 8; ++i) a[i] = ap[i * 128 + k];
        const float bv[8] = {b0.x, b0.y, b0.z, b0.w, b1.x, b1.y, b1.z, b1.w};
#pragma unroll
        for (int i = 0; i < 8; ++i)
#pragma unroll
            for (int j = 0; j < 8; ++j)
                acc[i][j] = fmaf(a[i], bv[j], acc[i][j]);
    }
}

// K=128, N=64 gemm: thread = 4 rows x 8 cols (tr=tid>>3 in 0..31, tc=tid&7)
__device__ __forceinline__ void gemm_K128_N64(const float* __restrict__ As,
                                              const float* __restrict__ Ws,
                                              float acc[4][8]) {
    const int tc = threadIdx.x & 7;
    const int tr = threadIdx.x >> 3;
    const float* ap = As + tr * 4 * 128;
    const float* bp = Ws + tc * 8;
#pragma unroll 4
    for (int k = 0; k < 128; ++k) {
        const float4 b0 = *reinterpret_cast<const float4*>(bp + k * 64);
        const float4 b1 = *reinterpret_cast<const float4*>(bp + k * 64 + 4);
        float a[4];
#pragma unroll
        for (int i = 0; i < 4; ++i) a[i] = ap[i * 128 + k];
        const float bv[8] = {b0.x, b0.y, b0.z, b0.w, b1.x, b1.y, b1.z, b1.w};
#pragma unroll
        for (int i = 0; i < 4; ++i)
#pragma unroll
            for (int j = 0; j < 8; ++j)
                acc[i][j] = fmaf(a[i], bv[j], acc[i][j]);
    }
}

// Load a 128x128 fp32 tile (row stride ld) into smem
__device__ __forceinline__ void load_tile(float* dst, const float* __restrict__ src,
                                          int ld) {
    for (int idx = threadIdx.x; idx < 128 * 32; idx += 256) {
        const int r = idx >> 5;
        const int c4 = idx & 31;
        reinterpret_cast<float4*>(dst)[(r << 5) + c4] =
            *reinterpret_cast<const float4*>(src + (size_t)r * ld + (c4 << 2));
    }
}

// Load a 128x64 tile (contiguous rows of 64) into cols 0..63 of As (stride 128)
__device__ __forceinline__ void load_tile64(float* dst, const float* __restrict__ src) {
    for (int idx = threadIdx.x; idx < 128 * 16; idx += 256) {
        const int r = idx >> 4;
        const int c4 = idx & 15;
        reinterpret_cast<float4*>(dst)[(r << 5) + c4] =
            *reinterpret_cast<const float4*>(src + (size_t)r * 64 + (c4 << 2));
    }
}

// Load a 64x128 fp32 slab (row stride ld) into smem
__device__ __forceinline__ void load_half(float* dst, const float* __restrict__ src,
                                          int ld) {
    for (int idx = threadIdx.x; idx < 64 * 32; idx += 256) {
        const int r = idx >> 5;
        const int c4 = idx & 31;
        reinterpret_cast<float4*>(dst)[(r << 5) + c4] =
            *reinterpret_cast<const float4*>(src + (size_t)r * ld + (c4 << 2));
    }
}

// linear copy of 8192 floats (e.g. full [128,64] or [64,128] weight)
__device__ __forceinline__ void load_lin8k(float* dst, const float* __restrict__ src) {
    for (int idx = threadIdx.x; idx < 2048; idx += 256)
        reinterpret_cast<float4*>(dst)[idx] =
            reinterpret_cast<const float4*>(src)[idx];
}

__device__ __forceinline__ void zero_acc(float acc[8][8]) {
#pragma unroll
    for (int i = 0; i < 8; ++i)
#pragma unroll
        for (int j = 0; j < 8; ++j) acc[i][j] = 0.f;
}

// full 128-deep GEMM as two 64-row slabs streamed through Ws
__device__ __forceinline__ void gemm128_slabs(const float* As, float* Ws,
                                              const float* __restrict__ W,
                                              int ldw, float acc[8][8]) {
#pragma unroll
    for (int h = 0; h < 2; ++h) {
        load_half(Ws, W + (size_t)(h * 64) * ldw, ldw);
        __syncthreads();
        gemm64(As, Ws, h * 64, acc);
        __syncthreads();
    }
}

// ---------------------------------------------------------------------------
// Kernel A: x_phi = x@Wx+bx; PEq = x_phi@Weq + beq;
//           PI = x_phi@Wih_x + bih + bhh + bihz
// grid (4 btiles, T, C), 256 threads, 96KB dynamic smem
// ---------------------------------------------------------------------------
__global__ void __launch_bounds__(256, 2) kernelA(
    const float* __restrict__ x, const float* __restrict__ Wx,
    const float* __restrict__ bx, const float* __restrict__ Wih,
    const float* __restrict__ bih, const float* __restrict__ bhh) {
    extern __shared__ float sm[];
    float* As = sm;                // 128x128
    float* Ws = sm + 128 * 128;    // 8192-float slab
    const int bt = blockIdx.x, t = blockIdx.y, c = blockIdx.z;
    const long rg0 = ((long)(c * T_ + t) * B_ + bt * 128);
    const int tc = threadIdx.x & 15, tr = threadIdx.x >> 4;

    load_tile(As, x + rg0 * F_, F_);

    float acc[8][8];
    zero_acc(acc);
    gemm128_slabs(As, Ws, Wx + (size_t)c * F_ * HX_, HX_, acc);  // x_phi

    // write x_phi (+bx) back into As (trailing sync above protects reads)
#pragma unroll
    for (int i = 0; i < 8; ++i)
#pragma unroll
        for (int j = 0; j < 8; ++j)
            As[(tr * 8 + i) * 128 + tc * 8 + j] = acc[i][j] + bx[c * HX_ + tc * 8 + j];

    // PEq = x_phi @ Weq + beq  (N=64)
    load_lin8k(Ws, g_Weq + c * HX_ * L_);
    __syncthreads();
    {
        float acc4[4][8];
#pragma unroll
        for (int i = 0; i < 4; ++i)
#pragma unroll
            for (int j = 0; j < 8; ++j) acc4[i][j] = 0.f;
        gemm_K128_N64(As, Ws, acc4);
        const int qc = threadIdx.x & 7, qr = threadIdx.x >> 3;
#pragma unroll
        for (int i = 0; i < 4; ++i)
#pragma unroll
            for (int j = 0; j < 8; ++j)
                g_PEq[(rg0 + qr * 4 + i) * L_ + qc * 8 + j] =
                    acc4[i][j] + g_beq[c * L_ + qc * 8 + j];
    }
    __syncthreads();  // protect Ws before PI slabs

    // PI = x_phi @ Wih_x + bih + bhh + bihz (two 128-col halves)
#pragma unroll
    for (int half = 0; half < 2; ++half) {
        zero_acc(acc);
        gemm128_slabs(As, Ws, Wih + half * 128, H_, acc);
#pragma unroll
        for (int i = 0; i < 8; ++i)
#pragma unroll
            for (int j = 0; j < 8; ++j) {
                const int n = half * 128 + tc * 8 + j;
                g_PI[(rg0 + tr * 8 + i) * H_ + n] =
                    acc[i][j] + bih[n] + bhh[n] + g_bihz[n];
            }
    }
}

// ===========================================================================
// Kernel B: the recurrence (2 stages per step after folding).
// ===========================================================================
template <int K, int N>
__device__ __forceinline__ void mm4(const float* __restrict__ Wg,
                                    const float* __restrict__ a_s,
                                    float4 acc[RMAX_]) {
    constexpr int G = N / 4;      // thread groups (one per 4 columns)
    constexpr int P = 256 / G;    // k partitions
    constexpr int Ks = K / P;
    const int g = threadIdx.x % G;
    const int p = threadIdx.x / G;
    const float4* wp = reinterpret_cast<const float4*>(Wg) + (size_t)(p * Ks) * G + g;
    const float* ap = a_s + p * Ks;

    float4 w0 = wp[0 * G], w1 = wp[1 * G], w2 = wp[2 * G], w3 = wp[3 * G];
#pragma unroll 1
    for (int k = 0; k < Ks; k += 4) {
        float4 n0, n1, n2, n3;
        if (k + 4 < Ks) {
            n0 = wp[(k + 4) * G];
            n1 = wp[(k + 5) * G];
            n2 = wp[(k + 6) * G];
            n3 = wp[(k + 7) * G];
        }
#pragma unroll
        for (int r = 0; r < RMAX_; ++r) {
            const float4 a = *reinterpret_cast<const float4*>(ap + r * K + k);
            acc[r].x = fmaf(a.x, w0.x, acc[r].x);
            acc[r].y = fmaf(a.x, w0.y, acc[r].y);
            acc[r].z = fmaf(a.x, w0.z, acc[r].z);
            acc[r].w = fmaf(a.x, w0.w, acc[r].w);
            acc[r].x = fmaf(a.y, w1.x, acc[r].x);
            acc[r].y = fmaf(a.y, w1.y, acc[r].y);
            acc[r].z = fmaf(a.y, w1.z, acc[r].z);
            acc[r].w = fmaf(a.y, w1.w, acc[r].w);
            acc[r].x = fmaf(a.z, w2.x, acc[r].x);
            acc[r].y = fmaf(a.z, w2.y, acc[r].y);
            acc[r].z = fmaf(a.z, w2.z, acc[r].z);
            acc[r].w = fmaf(a.z, w2.w, acc[r].w);
            acc[r].x = fmaf(a.w, w3.x, acc[r].x);
            acc[r].y = fmaf(a.w, w3.y, acc[r].y);
            acc[r].z = fmaf(a.w, w3.z, acc[r].z);
            acc[r].w = fmaf(a.w, w3.w, acc[r].w);
        }
        w0 = n0; w1 = n1; w2 = n2; w3 = n3;
    }
}

template <int N>
__device__ __forceinline__ void store_scr(float* __restrict__ scr,
                                          const float4 acc[RMAX_]) {
    const int g = threadIdx.x % (N / 4);
    const int p = threadIdx.x / (N / 4);
#pragma unroll
    for (int r = 0; r < RMAX_; ++r)
        *reinterpret_cast<float4*>(scr + (size_t)(p * RMAX_ + r) * N + 4 * g) = acc[r];
}

__device__ __forceinline__ void zero4(float4 acc[RMAX_]) {
#pragma unroll
    for (int r = 0; r < RMAX_; ++r) acc[r] = make_float4(0.f, 0.f, 0.f, 0.f);
}

__global__ void __launch_bounds__(256) kernelB(
    const float* __restrict__ Whh, const float* __restrict__ h0) {
    __shared__ __align__(16) float hs[RMAX_ * H_];
    __shared__ __align__(16) float zs[RMAX_ * L_];
    __shared__ __align__(16) float scr[RMAX_ * 1024];  // P*N == 1024 both stages

    const int c = blockIdx.y;
    // overlapping coverage: duplicated rows compute identical values.
    const int r0 = (blockIdx.x * (B_ - RMAX_)) / (NB_ - 1);
    const int tid = threadIdx.x;

    for (int idx = tid; idx < RMAX_ * H_; idx += 256)
        hs[idx] = h0[(size_t)(c * B_ + r0) * H_ + idx];
    __syncthreads();

    const float* Wcomb = g_Wcomb + c * H_ * L_;
    float4 acc[RMAX_];

    long rg0 = (long)c * T_ * B_ + r0;
    for (int t = 0; t < T_; ++t, rg0 += B_) {
        // ---- S1: z = PEq + h @ Wcomb   (K=256, N=64, P=16)
        zero4(acc);
        mm4<256, 64>(Wcomb, hs, acc);
        store_scr<64>(scr, acc);
        // store Hs[t] = h (pre-update) while partials land
        for (int idx = tid; idx < RMAX_ * H_; idx += 256)
            g_Hs[rg0 * H_ + idx] = hs[idx];
        __syncthreads();
        for (int idx = tid; idx < RMAX_ * L_; idx += 256) {
            const int r = idx >> 6, n = idx & 63;
            float s = g_PEq[rg0 * L_ + idx];
#pragma unroll
            for (int p = 0; p < 16; ++p) s += scr[(size_t)(p * RMAX_ + r) * 64 + n];
            zs[idx] = s;
            g_Zs[rg0 * L_ + idx] = s;
        }
        __syncthreads();

        // ---- S2: h' = tanh(PI + z@Wihz + h@Whh)   (N=256, P=4)
        zero4(acc);
        mm4<64, 256>(g_Wihz, zs, acc);
        mm4<256, 256>(Whh, hs, acc);
        store_scr<256>(scr, acc);
        __syncthreads();
        for (int idx = tid; idx < RMAX_ * H_; idx += 256) {
            const int r = idx >> 8, n = idx & 255;
            float s = g_PI[rg0 * H_ + idx];
#pragma unroll
            for (int p = 0; p < 4; ++p) s += scr[(size_t)(p * RMAX_ + r) * 256 + n];
            hs[idx] = tanhf(s);
        }
        __syncthreads();
    }
}

// ---------------------------------------------------------------------------
// Kernel C: out = Zs@Wzo + Hs@Who + bo
// grid (4 btiles, T, C), 256 threads, 96KB dynamic smem
// ---------------------------------------------------------------------------
__global__ void __launch_bounds__(256, 2) kernelC(float* __restrict__ out) {
    extern __shared__ float sm[];
    float* As = sm;
    float* Ws = sm + 128 * 128;
    const int bt = blockIdx.x, t = blockIdx.y, c = blockIdx.z;
    const long rg0 = ((long)(c * T_ + t) * B_ + bt * 128);
    const int tc = threadIdx.x & 15, tr = threadIdx.x >> 4;

    float acc[8][8];
    zero_acc(acc);

    // h part: two 128-row slices of Who (K=256 total)
    load_tile(As, g_Hs + rg0 * H_, H_);
    gemm128_slabs(As, Ws, g_Who + (size_t)c * H_ * F_, F_, acc);
    load_tile(As, g_Hs + rg0 * H_ + 128, H_);
    gemm128_slabs(As, Ws, g_Who + (size_t)c * H_ * F_ + 128 * F_, F_, acc);

    // z part: K=64
    load_tile64(As, g_Zs + rg0 * L_);
    load_lin8k(Ws, g_Wzo + c * L_ * F_);   // [64,128]
    __syncthreads();
    gemm64(As, Ws, 0, acc);

#pragma unroll
    for (int i = 0; i < 8; ++i)
#pragma unroll
        for (int j = 0; j < 8; ++j)
            out[(rg0 + tr * 8 + i) * F_ + tc * 8 + j] =
                acc[i][j] + g_bo[c * F_ + tc * 8 + j];
}

// ---------------------------------------------------------------------------
extern "C" void kernel_launch(void* const* d_in, const int* in_sizes, int n_in,
                              void* d_out, int out_size) {
    (void)in_sizes; (void)n_in; (void)out_size;
    const float* x        = (const float*)d_in[0];
    const float* phi_x_W  = (const float*)d_in[1];
    const float* phi_x_b  = (const float*)d_in[2];
    const float* enc_W    = (const float*)d_in[3];
    const float* enc_b    = (const float*)d_in[4];
    const float* enc_mu_W = (const float*)d_in[5];
    const float* enc_mu_b = (const float*)d_in[6];
    const float* phi_z_W  = (const float*)d_in[7];
    const float* phi_z_b  = (const float*)d_in[8];
    const float* dec_W    = (const float*)d_in[9];
    const float* dec_b    = (const float*)d_in[10];
    const float* dec_mu_W = (const float*)d_in[11];
    const float* dec_mu_b = (const float*)d_in[12];
    const float* rnn_Wih  = (const float*)d_in[13];
    const float* rnn_Whh  = (const float*)d_in[14];
    const float* rnn_bih  = (const float*)d_in[15];
    const float* rnn_bhh  = (const float*)d_in[16];
    const float* h0       = (const float*)d_in[17];
    float* out = (float*)d_out;

    const size_t smem = (128 * 128 + 64 * 128) * sizeof(float);  // 96 KB
    cudaFuncSetAttribute(kernelA, cudaFuncAttributeMaxDynamicSharedMemorySize, (int)smem);
    cudaFuncSetAttribute(kernelC, cudaFuncAttributeMaxDynamicSharedMemorySize, (int)smem);

    kernelF1<<<29, 256>>>(enc_W, enc_b, enc_mu_W, enc_mu_b, phi_z_W, phi_z_b,
                          dec_W, dec_b, rnn_Wih);
    kernelF2<<<18, 256>>>(dec_W, dec_mu_W, dec_mu_b);
    kernelA<<<dim3(4, T_, C_), 256, smem>>>(x, phi_x_W, phi_x_b,
                                            rnn_Wih, rnn_bih, rnn_bhh);
    kernelB<<<dim3(NB_, C_), 256>>>(rnn_Whh, h0);
    kernelC<<<dim3(4, T_, C_), 256, smem>>>(out);
}